// round 16
// baseline (speedup 1.0000x reference)
#include <cuda_runtime.h>
#include <cstdint>

#define NMAX 8192
#define HDIM 128
#define RPB 32      // rows per gemm block == hub-partial chunk
#define CHUNK 2048  // sort chunk per block
#define MAXCH (NMAX / RPB)

// ============================================================================
// Device scratch
// ============================================================================
__device__ int   g_edges[2][NMAX * 5];
__device__ float g_hA[NMAX * HDIM];
__device__ float g_hB[NMAX * HDIM];
__device__ float g_xs[2][NMAX * HDIM];
__device__ int   g_perm[2][NMAX];
__device__ int   g_indeg[NMAX];
__device__ float g_dinv[NMAX];
__device__ float g_z[NMAX];
__device__ float g_score[NMAX];
__device__ unsigned long long g_keys[NMAX];
__device__ int   g_idx[NMAX];
__device__ float g_sv[NMAX];
__device__ int   g_newid[NMAX];
__device__ int   g_hubs[5];
__device__ int   g_nhubs;
__device__ float g_part[5 * HDIM * MAXCH];   // [k][f][ch]
__device__ __align__(8) unsigned char g_mask[NMAX];
__device__ unsigned g_rmax[3][HDIM];
__device__ float g_rsum[3][HDIM];

// ============================================================================
// Helpers
// ============================================================================
__device__ __forceinline__ unsigned ordf(float v) {
    unsigned u = __float_as_uint(v);
    return (u & 0x80000000u) ? ~u : (u | 0x80000000u);
}
__device__ __forceinline__ float deco(unsigned e) {
    unsigned u = (e & 0x80000000u) ? (e & 0x7fffffffu) : ~e;
    return __uint_as_float(u);
}
__device__ __forceinline__ unsigned long long pk2(float x, float y) {
    unsigned long long r;
    asm("mov.b64 %0, {%1, %2};" : "=l"(r)
        : "r"(__float_as_uint(x)), "r"(__float_as_uint(y)));
    return r;
}
__device__ __forceinline__ void up2(unsigned long long v, float& x, float& y) {
    unsigned a, b;
    asm("mov.b64 {%0, %1}, %2;" : "=r"(a), "=r"(b) : "l"(v));
    x = __uint_as_float(a);
    y = __uint_as_float(b);
}
__device__ __forceinline__ void fma2(unsigned long long& c,
                                     unsigned long long a,
                                     unsigned long long b) {
    asm("fma.rn.f32x2 %0, %1, %2, %3;" : "=l"(c) : "l"(a), "l"(b), "l"(c));
}

// ============================================================================
// Init: stage-0 edges, closed-form indeg, AND closed-form stage-0
// dinv/mask/hubs (hubs = {0,1,2,3,4}; mask = r<=4 ? 0x1F : 0x0F).
// Expressions identical to dinvhubsmask's.
// ============================================================================
__global__ void init_kernel(int* __restrict__ eout, int* __restrict__ indeg,
                            float* __restrict__ dinv, unsigned char* __restrict__ mask) {
    int i = blockIdx.x * 256 + threadIdx.x;
    if (i < NMAX) {
        int pos = 0;
        #pragma unroll
        for (int j = 0; j < 5; j++)
            if (j != i && pos < 4) eout[i * 5 + (pos++)] = j;
        eout[i * 5 + 4] = -1;
        int d = (i < 4) ? (NMAX - 1) : ((i == 4) ? 4 : 0);
        indeg[i] = d;
        float deg = 1.f + (float)d;
        dinv[i] = 1.0f / sqrtf(deg);
        mask[i] = (i <= 4) ? 0x1F : 0x0F;
    }
    if (i < 3 * HDIM) {
        (&g_rmax[0][0])[i] = 0u;
        (&g_rsum[0][0])[i] = 0.f;
    }
    if (i == 0) {
        g_nhubs = 5;
        #pragma unroll
        for (int k = 0; k < 5; k++) g_hubs[k] = k;
    }
}

// ============================================================================
// dinv + hub detection + per-row mask (stages 1,2)
// ============================================================================
__global__ void dinvhubsmask_kernel(const int* __restrict__ indeg,
                                    const int* __restrict__ edges,
                                    float* __restrict__ dinv,
                                    unsigned char* __restrict__ mask, int n) {
    __shared__ int cnt;
    __shared__ int sl[16];
    __shared__ int shub[5];
    int t = threadIdx.x;
    if (t == 0) cnt = 0;
    __syncthreads();
    for (int i = t; i < n; i += 1024) {
        int d = indeg[i];
        float deg = 1.f + (float)d;
        dinv[i] = 1.0f / sqrtf(deg);
        if (d > 0) {
            int p = atomicAdd(&cnt, 1);
            if (p < 16) sl[p] = i;
        }
    }
    __syncthreads();
    if (t == 0) {
        int m = cnt < 5 ? cnt : 5;
        for (int i = 1; i < m; i++) {
            int v = sl[i], j = i - 1;
            while (j >= 0 && sl[j] > v) { sl[j + 1] = sl[j]; j--; }
            sl[j + 1] = v;
        }
        g_nhubs = m;
        #pragma unroll
        for (int k = 0; k < 5; k++) {
            int v = (k < m) ? sl[k] : -1;
            g_hubs[k] = v;
            shub[k] = v;
        }
    }
    __syncthreads();
    for (int r = t; r < n; r += 1024) {
        int e0 = edges[r * 5 + 0], e1 = edges[r * 5 + 1], e2 = edges[r * 5 + 2];
        int e3 = edges[r * 5 + 3], e4 = edges[r * 5 + 4];
        unsigned m = 0;
        #pragma unroll
        for (int k = 0; k < 5; k++) {
            int hv = shub[k];
            bool hit = (hv >= 0) &&
                       (e0 == hv || e1 == hv || e2 == hv || e3 == hv || e4 == hv || r == hv);
            if (hit) m |= 1u << k;
        }
        mask[r] = (unsigned char)m;
    }
}

// ============================================================================
// Mega GEMM (FFMA2) + base hA + hub partials + zdot/score/keys epilogue.
// part layout: [k][f][ch] (same values/order as R15, transposed addressing).
// ============================================================================
__global__ void gemmF_kernel(const float* __restrict__ h, const float* __restrict__ W,
                             const float* __restrict__ b, const float* __restrict__ Wp,
                             const float* __restrict__ bp, const float* __restrict__ dinv,
                             const unsigned char* __restrict__ mask,
                             float* __restrict__ hA, float* __restrict__ part,
                             float* __restrict__ z, float* __restrict__ score,
                             unsigned long long* __restrict__ keys) {
    __shared__ __align__(16) float sbuf[HDIM * 34];
    __shared__ float spart[5 * HDIM];
    __shared__ float sdi[RPB];
    __shared__ float sWp[HDIM];
    const int t = threadIdx.x;
    const int c = t & 127;
    const int rb = (t >> 7) * 16;
    const int r0 = blockIdx.x * RPB;
    if (t < RPB) sdi[t] = dinv[r0 + t];
    if (t < HDIM) sWp[t] = Wp[t];
    #pragma unroll
    for (int l = 0; l < 16; l++) {
        int id = l * 256 + t;
        int rr = id >> 7, cc = id & 127;
        sbuf[cc * 34 + rr] = h[(size_t)(r0 + rr) * HDIM + cc];
    }
    __syncthreads();

    unsigned long long acc2[8];
    #pragma unroll
    for (int p = 0; p < 8; p++) acc2[p] = 0ull;
    #pragma unroll
    for (int k0 = 0; k0 < HDIM; k0 += 8) {
        float wv[8];
        #pragma unroll
        for (int q = 0; q < 8; q++) wv[q] = W[(k0 + q) * HDIM + c];
        #pragma unroll
        for (int q = 0; q < 8; q++) {
            unsigned long long w2 = pk2(wv[q], wv[q]);
            const float2* hp = (const float2*)&sbuf[(k0 + q) * 34 + rb];
            #pragma unroll
            for (int p = 0; p < 8; p++) {
                float2 h2 = hp[p];
                fma2(acc2[p], pk2(h2.x, h2.y), w2);
            }
        }
    }
    __syncthreads();

    unsigned long long um0 = *(const unsigned long long*)(mask + r0 + rb);
    unsigned long long um1 = *(const unsigned long long*)(mask + r0 + rb + 8);

    float bc = b[c];
    float hp5[5] = {0.f, 0.f, 0.f, 0.f, 0.f};
    #pragma unroll
    for (int p = 0; p < 8; p++) {
        float a0, a1;
        up2(acc2[p], a0, a1);
        int rr0 = rb + 2 * p, rr1 = rr0 + 1;
        float d0 = sdi[rr0], d1 = sdi[rr1];
        float v0 = fmaxf(fmaf(d0 * d0, a0, bc), 0.f);
        float v1 = fmaxf(fmaf(d1 * d1, a1, bc), 0.f);
        hA[(size_t)(r0 + rr0) * HDIM + c] = v0;
        hA[(size_t)(r0 + rr1) * HDIM + c] = v1;
        sbuf[rr0 * HDIM + c] = v0;
        sbuf[rr1 * HDIM + c] = v1;
        unsigned long long umm = (2 * p < 8) ? um0 : um1;
        unsigned mb0 = (unsigned)(umm >> (8 * ((2 * p) & 7))) & 0xffu;
        unsigned mb1 = (unsigned)(umm >> (8 * ((2 * p + 1) & 7))) & 0xffu;
        float w0 = d0 * a0, w1 = d1 * a1;
        #pragma unroll
        for (int k = 0; k < 5; k++) {
            if ((mb0 >> k) & 1u) hp5[k] += w0;
            if ((mb1 >> k) & 1u) hp5[k] += w1;
        }
    }
    if (rb == 16) {
        #pragma unroll
        for (int k = 0; k < 5; k++) spart[k * HDIM + c] = hp5[k];
    }
    __syncthreads();
    if (rb == 0) {
        #pragma unroll
        for (int k = 0; k < 5; k++)
            part[((size_t)k * HDIM + c) * MAXCH + blockIdx.x] =
                hp5[k] + spart[k * HDIM + c];
    }

    int w = t >> 5, lane = t & 31;
    float bp0 = bp[0];
    #pragma unroll
    for (int q = 0; q < 4; q++) {
        int rr = w * 4 + q;
        float s = 0.f;
        #pragma unroll
        for (int kk = 0; kk < 4; kk++)
            s = fmaf(sbuf[rr * HDIM + lane + 32 * kk], sWp[lane + 32 * kk], s);
        #pragma unroll
        for (int o = 16; o > 0; o >>= 1) s += __shfl_down_sync(0xffffffffu, s, o);
        if (lane == 0) {
            int r = r0 + rr;
            z[r] = s;
            float dc = sdi[rr];
            float sc = fmaf(dc * dc, s, bp0);
            score[r] = sc;
            keys[r] = ((unsigned long long)(~ordf(sc)) << 32) | (unsigned)r;
        }
    }
}

// ============================================================================
// Hub fixup (5 blocks x 1024 threads, 8-slice ascending regroup; per-thread
// slice is now a CONTIGUOUS run of chunks -> fully unrollable independent
// loads; sum order identical to R13/R15)
// ============================================================================
__global__ void hubfixF_kernel(const float* __restrict__ part, int nchunks,
                               const float* __restrict__ dinv,
                               const float* __restrict__ b, const float* __restrict__ Wp,
                               float* __restrict__ hA, float* __restrict__ z) {
    int k = blockIdx.x;
    if (k >= g_nhubs) return;
    __shared__ float pp[8][HDIM];
    __shared__ float hv[HDIM];
    int t = threadIdx.x;
    int j = t >> 7, f = t & 127;
    int per = nchunks >> 3;
    const float* base = part + ((size_t)k * HDIM + f) * MAXCH + j * per;
    float S = 0.f;
    #pragma unroll 8
    for (int ch = 0; ch < per; ch++) S += base[ch];
    pp[j][f] = S;
    __syncthreads();
    if (j == 0) {
        float T = S;
        #pragma unroll
        for (int q = 1; q < 8; q++) T += pp[q][f];
        int c = g_hubs[k];
        float v = fmaf(dinv[c], T, b[f]);
        v = fmaxf(v, 0.f);
        hA[(size_t)c * HDIM + f] = v;
        hv[f] = v;
    }
    __syncthreads();
    if (t < 32) {
        float s = 0.f;
        #pragma unroll
        for (int kk = 0; kk < 4; kk++)
            s = fmaf(hv[t + 32 * kk], Wp[t + 32 * kk], s);
        #pragma unroll
        for (int o = 16; o > 0; o >>= 1) s += __shfl_down_sync(0xffffffffu, s, o);
        if (t == 0) z[g_hubs[k]] = s;
    }
}

// R4-verbatim hub score + key pack
__global__ void hubfixSK_kernel(const float* __restrict__ z, const float* __restrict__ dinv,
                                const unsigned char* __restrict__ mask,
                                const float* __restrict__ bp,
                                float* __restrict__ score,
                                unsigned long long* __restrict__ keys, int n) {
    int k = blockIdx.x;
    if (k >= g_nhubs) return;
    int hub = g_hubs[k];
    __shared__ float red[256];
    int t = threadIdx.x;
    float p = 0.f;
    for (int r = t; r < n; r += 256) {
        if ((mask[r] >> k) & 1u) p += dinv[r] * z[r];
    }
    red[t] = p;
    __syncthreads();
    for (int o = 128; o > 0; o >>= 1) {
        if (t < o) red[t] += red[t + o];
        __syncthreads();
    }
    if (t == 0) {
        float sc = fmaf(dinv[hub], red[0], bp[0]);
        score[hub] = sc;
        keys[hub] = ((unsigned long long)(~ordf(sc)) << 32) | (unsigned)hub;
    }
}

// ============================================================================
// Multi-block bitonic sort, 2048-chunk + fused extract
// ============================================================================
__device__ __forceinline__ void do_extract2(const unsigned long long* sk, int g0, int t,
                                            const float* __restrict__ score,
                                            int* __restrict__ idx, float* __restrict__ sv,
                                            int* __restrict__ newid, int* __restrict__ indeg,
                                            int ksel) {
    #pragma unroll
    for (int h = 0; h < 2; h++) {
        int li = t + h * 1024;
        int i = g0 + li;
        int id = (int)(sk[li] & 0xffffffffull);
        newid[id] = (i < ksel) ? i : -1;
        if (i < ksel) {
            idx[i] = id;
            sv[i] = score[id];
            indeg[i] = 0;
        }
    }
}

__global__ void sort_local_kernel(unsigned long long* __restrict__ keys,
                                  const float* __restrict__ score,
                                  int* __restrict__ idx, float* __restrict__ sv,
                                  int* __restrict__ newid, int* __restrict__ indeg,
                                  int ksel, int do_ext) {
    __shared__ unsigned long long sk[CHUNK];
    int t = threadIdx.x;
    int g0 = blockIdx.x * CHUNK;
    sk[t] = keys[g0 + t];
    sk[t + 1024] = keys[g0 + t + 1024];
    __syncthreads();
    for (int k = 2; k <= CHUNK; k <<= 1) {
        for (int j = k >> 1; j > 0; j >>= 1) {
            int i = ((t / j) * 2 * j) + (t % j);
            int ixj = i + j;
            bool up = (((g0 + i) & k) == 0);
            unsigned long long a = sk[i], bb = sk[ixj];
            if ((a > bb) == up) { sk[i] = bb; sk[ixj] = a; }
            __syncthreads();
        }
    }
    keys[g0 + t] = sk[t];
    keys[g0 + t + 1024] = sk[t + 1024];
    if (do_ext) do_extract2(sk, g0, t, score, idx, sv, newid, indeg, ksel);
}

__global__ void sort_cross_kernel(unsigned long long* __restrict__ keys,
                                  int n, int k, int j) {
    int t = blockIdx.x * 256 + threadIdx.x;
    if (t >= n / 2) return;
    int i = ((t / j) * 2 * j) + (t % j);
    int ixj = i + j;
    bool up = ((i & k) == 0);
    unsigned long long a = keys[i], bb = keys[ixj];
    if ((a > bb) == up) { keys[i] = bb; keys[ixj] = a; }
}

__global__ void sort_finish_kernel(unsigned long long* __restrict__ keys, int k,
                                   const float* __restrict__ score,
                                   int* __restrict__ idx, float* __restrict__ sv,
                                   int* __restrict__ newid, int* __restrict__ indeg,
                                   int ksel, int do_ext) {
    __shared__ unsigned long long sk[CHUNK];
    int t = threadIdx.x;
    int g0 = blockIdx.x * CHUNK;
    sk[t] = keys[g0 + t];
    sk[t + 1024] = keys[g0 + t + 1024];
    __syncthreads();
    for (int j = 1024; j > 0; j >>= 1) {
        int i = ((t / j) * 2 * j) + (t % j);
        int ixj = i + j;
        bool up = (((g0 + i) & k) == 0);
        unsigned long long a = sk[i], bb = sk[ixj];
        if ((a > bb) == up) { sk[i] = bb; sk[ixj] = a; }
        __syncthreads();
    }
    keys[g0 + t] = sk[t];
    keys[g0 + t + 1024] = sk[t + 1024];
    if (do_ext) do_extract2(sk, g0, t, score, idx, sv, newid, indeg, ksel);
}

// ============================================================================
// Pool (32 new nodes/block)
// ============================================================================
__global__ void pool_kernel(const float* __restrict__ h, const float* __restrict__ xs,
                            const int* __restrict__ perm, const int* __restrict__ edges,
                            const int* __restrict__ idx, const float* __restrict__ sv,
                            const int* __restrict__ newid,
                            float* __restrict__ h2, float* __restrict__ xs2,
                            int* __restrict__ perm2, int* __restrict__ edges2,
                            int* __restrict__ indeg, int stage) {
    __shared__ int sidx[32];
    __shared__ float sg[32];
    int c = threadIdx.x;
    int a0 = blockIdx.x * 32;
    if (c < 32) {
        sidx[c] = idx[a0 + c];
        sg[c] = tanhf(sv[a0 + c]);
    }
    __syncthreads();
    float lmax = -3.4e38f, lsum = 0.f;
    for (int rr = 0; rr < 32; rr++) {
        int a = a0 + rr;
        int o = sidx[rr];
        float v = h[(size_t)o * HDIM + c] * sg[rr];
        h2[(size_t)a * HDIM + c] = v;
        xs2[(size_t)a * HDIM + c] = xs[(size_t)o * HDIM + c];
        lmax = fmaxf(lmax, v);
        lsum += v;
        if (c < 5) {
            int e = edges[o * 5 + c];
            int ne = (e >= 0) ? newid[e] : -1;
            edges2[a * 5 + c] = ne;
            if (ne >= 0) atomicAdd(&indeg[ne], 1);
        }
        if (c == 5) perm2[a] = (perm != nullptr) ? perm[o] : o;
    }
    atomicMax(&g_rmax[stage][c], ordf(lmax));
    atomicAdd(&g_rsum[stage][c], lsum);
}

// ============================================================================
// Tail: a3 densify (blocks 0..1023) + xs/perm copy (1024..1539) + MLP (1540)
// ============================================================================
__global__ void tail_kernel(const int* __restrict__ edges,
                            const float* __restrict__ xs, const int* __restrict__ perm,
                            const float* __restrict__ L1w, const float* __restrict__ L1b,
                            const float* __restrict__ L2w, const float* __restrict__ L2b,
                            const float* __restrict__ L3w, const float* __restrict__ L3b,
                            float* __restrict__ out) {
    int bidx = blockIdx.x;
    int t = threadIdx.x;
    if (bidx < 1024) {
        float* row = out + 40 + 1024 * HDIM + 1024 + (size_t)bidx * 1024;
        for (int i = t; i < 1024; i += 256) row[i] = 0.f;
        __syncthreads();
        if (t == 0) {
            row[bidx] = 1.f;
            #pragma unroll
            for (int e = 0; e < 5; e++) {
                int tgt = edges[bidx * 5 + e];
                if (tgt >= 0) row[tgt] = 1.f;
            }
        }
        return;
    }
    if (bidx < 1540) {
        int i = (bidx - 1024) * 256 + t;
        if (i < 1024 * HDIM) out[40 + i] = xs[i];
        else if (i < 1024 * HDIM + 1024)
            out[40 + 1024 * HDIM + (i - 1024 * HDIM)] = (float)perm[i - 1024 * HDIM];
        return;
    }
    __shared__ float zin[256], z1[128], z2[64], z3[40];
    if (t < 128) {
        zin[t] = deco(g_rmax[0][t]) + deco(g_rmax[1][t]) + deco(g_rmax[2][t]);
        zin[128 + t] = g_rsum[0][t] / 4096.f + g_rsum[1][t] / 2048.f + g_rsum[2][t] / 1024.f;
    }
    __syncthreads();
    if (t < 128) {
        float a = 0.f;
        for (int i = 0; i < 256; i++) a = fmaf(zin[i], L1w[i * 128 + t], a);
        z1[t] = fmaxf(a + L1b[t], 0.f);
    }
    __syncthreads();
    if (t < 64) {
        float a = 0.f;
        for (int i = 0; i < 128; i++) a = fmaf(z1[i], L2w[i * 64 + t], a);
        z2[t] = fmaxf(a + L2b[t], 0.f);
    }
    __syncthreads();
    if (t < 40) {
        float a = 0.f;
        for (int i = 0; i < 64; i++) a = fmaf(z2[i], L3w[i * 40 + t], a);
        z3[t] = a + L3b[t];
    }
    __syncthreads();
    if (t == 0) {
        float m = z3[0];
        for (int i = 1; i < 40; i++) m = fmaxf(m, z3[i]);
        float s = 0.f;
        for (int i = 0; i < 40; i++) s += expf(z3[i] - m);
        float l = m + logf(s);
        for (int i = 0; i < 40; i++) out[i] = z3[i] - l;
    }
}

// ============================================================================
// Host launcher
// ============================================================================
extern "C" void kernel_launch(void* const* d_in, const int* in_sizes, int n_in,
                              void* d_out, int out_size) {
    (void)in_sizes; (void)n_in; (void)out_size;
    const float* x0  = (const float*)d_in[0];
    const float* W[3]  = {(const float*)d_in[2], (const float*)d_in[4], (const float*)d_in[6]};
    const float* bb[3] = {(const float*)d_in[3], (const float*)d_in[5], (const float*)d_in[7]};
    const float* Wp[3] = {(const float*)d_in[8], (const float*)d_in[10], (const float*)d_in[12]};
    const float* bp[3] = {(const float*)d_in[9], (const float*)d_in[11], (const float*)d_in[13]};
    const float* L1w = (const float*)d_in[14];
    const float* L1b = (const float*)d_in[15];
    const float* L2w = (const float*)d_in[16];
    const float* L2b = (const float*)d_in[17];
    const float* L3w = (const float*)d_in[18];
    const float* L3b = (const float*)d_in[19];
    float* out = (float*)d_out;

    float *p_hA, *p_hB, *p_dinv, *p_z, *p_score, *p_sv, *p_xsb, *p_part;
    int *p_edgesb, *p_indeg, *p_idx, *p_newid, *p_permb;
    unsigned char* p_mask;
    unsigned long long* p_keys;
    cudaGetSymbolAddress((void**)&p_edgesb, g_edges);
    cudaGetSymbolAddress((void**)&p_hA, g_hA);
    cudaGetSymbolAddress((void**)&p_hB, g_hB);
    cudaGetSymbolAddress((void**)&p_xsb, g_xs);
    cudaGetSymbolAddress((void**)&p_permb, g_perm);
    cudaGetSymbolAddress((void**)&p_indeg, g_indeg);
    cudaGetSymbolAddress((void**)&p_dinv, g_dinv);
    cudaGetSymbolAddress((void**)&p_z, g_z);
    cudaGetSymbolAddress((void**)&p_score, g_score);
    cudaGetSymbolAddress((void**)&p_keys, g_keys);
    cudaGetSymbolAddress((void**)&p_idx, g_idx);
    cudaGetSymbolAddress((void**)&p_sv, g_sv);
    cudaGetSymbolAddress((void**)&p_newid, g_newid);
    cudaGetSymbolAddress((void**)&p_part, g_part);
    cudaGetSymbolAddress((void**)&p_mask, g_mask);

    int* p_edges[2] = {p_edgesb, p_edgesb + NMAX * 5};
    float* p_xs[2] = {p_xsb, p_xsb + (size_t)NMAX * HDIM};
    int* p_perm[2] = {p_permb, p_permb + NMAX};

    // init: edges0, closed-form indeg + stage-0 dinv/mask/hubs, readout zero
    init_kernel<<<NMAX / 256, 256>>>(p_edges[0], p_indeg, p_dinv, p_mask);

    for (int s = 0; s < 3; s++) {
        int n = NMAX >> s;
        int k = n >> 1;
        int nchunks = n / RPB;
        int* ecur = p_edges[s & 1];
        int* enext = p_edges[(s + 1) & 1];
        const float* hin = (s == 0) ? x0 : p_hB;
        const float* xin = (s == 0) ? x0 : p_xs[(s - 1) & 1];
        const int* pin = (s == 0) ? nullptr : p_perm[(s - 1) & 1];

        if (s > 0)
            dinvhubsmask_kernel<<<1, 1024>>>(p_indeg, ecur, p_dinv, p_mask, n);

        gemmF_kernel<<<nchunks, 256>>>(hin, W[s], bb[s], Wp[s], bp[s], p_dinv,
                                       p_mask, p_hA, p_part, p_z, p_score, p_keys);
        hubfixF_kernel<<<5, 1024>>>(p_part, nchunks, p_dinv, bb[s], Wp[s], p_hA, p_z);
        hubfixSK_kernel<<<5, 256>>>(p_z, p_dinv, p_mask, bp[s], p_score, p_keys, n);

        // multiblock bitonic sort, 2048-chunk (+ fused extract on final pass)
        int nblk = n / CHUNK;
        sort_local_kernel<<<nblk, 1024>>>(p_keys, p_score, p_idx, p_sv,
                                          p_newid, p_indeg, k, (n == CHUNK) ? 1 : 0);
        for (int kk = 2 * CHUNK; kk <= n; kk <<= 1) {
            for (int j = kk >> 1; j >= CHUNK; j >>= 1)
                sort_cross_kernel<<<(n / 2 + 255) / 256, 256>>>(p_keys, n, kk, j);
            sort_finish_kernel<<<nblk, 1024>>>(p_keys, kk, p_score, p_idx, p_sv,
                                               p_newid, p_indeg, k,
                                               (kk == n) ? 1 : 0);
        }

        pool_kernel<<<k / 32, 128>>>(p_hA, xin, pin, ecur, p_idx, p_sv, p_newid,
                                     p_hB, p_xs[s & 1], p_perm[s & 1], enext,
                                     p_indeg, s);
    }

    tail_kernel<<<1541, 256>>>(p_edges[1], p_xs[0], p_perm[0],
                               L1w, L1b, L2w, L2b, L3w, L3b, out);
}

// round 17
// speedup vs baseline: 1.0958x; 1.0958x over previous
#include <cuda_runtime.h>
#include <cstdint>

#define NMAX 8192
#define HDIM 128
#define RPB 32      // rows per gemm block == hub-partial chunk
#define CHUNK 2048  // sort chunk per block
#define MAXCH (NMAX / RPB)

// ============================================================================
// Device scratch
// ============================================================================
__device__ int   g_edges[2][NMAX * 5];
__device__ float g_hA[NMAX * HDIM];
__device__ float g_hB[NMAX * HDIM];
__device__ float g_xs[2][NMAX * HDIM];
__device__ int   g_perm[2][NMAX];
__device__ int   g_indeg[NMAX];
__device__ float g_dinv[NMAX];
__device__ float g_z[NMAX];
__device__ float g_score[NMAX];
__device__ unsigned long long g_keys[NMAX];
__device__ int   g_idx[NMAX];
__device__ float g_sv[NMAX];
__device__ int   g_newid[NMAX];
__device__ int   g_hubs[5];
__device__ int   g_nhubs;
__device__ float g_part[MAXCH * 5 * HDIM];   // [ch][k][f]  (R15 layout)
__device__ __align__(8) unsigned char g_mask[NMAX];
__device__ unsigned g_rmax[3][HDIM];
__device__ float g_rsum[3][HDIM];

// ============================================================================
// Helpers
// ============================================================================
__device__ __forceinline__ unsigned ordf(float v) {
    unsigned u = __float_as_uint(v);
    return (u & 0x80000000u) ? ~u : (u | 0x80000000u);
}
__device__ __forceinline__ float deco(unsigned e) {
    unsigned u = (e & 0x80000000u) ? (e & 0x7fffffffu) : ~e;
    return __uint_as_float(u);
}
__device__ __forceinline__ unsigned long long pk2(float x, float y) {
    unsigned long long r;
    asm("mov.b64 %0, {%1, %2};" : "=l"(r)
        : "r"(__float_as_uint(x)), "r"(__float_as_uint(y)));
    return r;
}
__device__ __forceinline__ void up2(unsigned long long v, float& x, float& y) {
    unsigned a, b;
    asm("mov.b64 {%0, %1}, %2;" : "=r"(a), "=r"(b) : "l"(v));
    x = __uint_as_float(a);
    y = __uint_as_float(b);
}
__device__ __forceinline__ void fma2(unsigned long long& c,
                                     unsigned long long a,
                                     unsigned long long b) {
    asm("fma.rn.f32x2 %0, %1, %2, %3;" : "=l"(c) : "l"(a), "l"(b), "l"(c));
}

// ============================================================================
// Init: stage-0 edges, closed-form indeg, AND closed-form stage-0
// dinv/mask/hubs (hubs = {0,1,2,3,4}; mask = i<=4 ? 0x1F : 0x0F).
// Values provably identical to dinvhubsmask's stage-0 output.
// ============================================================================
__global__ void init_kernel(int* __restrict__ eout, int* __restrict__ indeg,
                            float* __restrict__ dinv, unsigned char* __restrict__ mask) {
    int i = blockIdx.x * 256 + threadIdx.x;
    if (i < NMAX) {
        int pos = 0;
        #pragma unroll
        for (int j = 0; j < 5; j++)
            if (j != i && pos < 4) eout[i * 5 + (pos++)] = j;
        eout[i * 5 + 4] = -1;
        int d = (i < 4) ? (NMAX - 1) : ((i == 4) ? 4 : 0);
        indeg[i] = d;
        float deg = 1.f + (float)d;
        dinv[i] = 1.0f / sqrtf(deg);
        mask[i] = (i <= 4) ? 0x1F : 0x0F;
    }
    if (i < 3 * HDIM) {
        (&g_rmax[0][0])[i] = 0u;
        (&g_rsum[0][0])[i] = 0.f;
    }
    if (i == 0) {
        g_nhubs = 5;
        #pragma unroll
        for (int k = 0; k < 5; k++) g_hubs[k] = k;
    }
}

// ============================================================================
// dinv + hub detection + per-row mask (stages 1,2 only)
// ============================================================================
__global__ void dinvhubsmask_kernel(const int* __restrict__ indeg,
                                    const int* __restrict__ edges,
                                    float* __restrict__ dinv,
                                    unsigned char* __restrict__ mask, int n) {
    __shared__ int cnt;
    __shared__ int sl[16];
    __shared__ int shub[5];
    int t = threadIdx.x;
    if (t == 0) cnt = 0;
    __syncthreads();
    for (int i = t; i < n; i += 1024) {
        int d = indeg[i];
        float deg = 1.f + (float)d;
        dinv[i] = 1.0f / sqrtf(deg);
        if (d > 0) {
            int p = atomicAdd(&cnt, 1);
            if (p < 16) sl[p] = i;
        }
    }
    __syncthreads();
    if (t == 0) {
        int m = cnt < 5 ? cnt : 5;
        for (int i = 1; i < m; i++) {
            int v = sl[i], j = i - 1;
            while (j >= 0 && sl[j] > v) { sl[j + 1] = sl[j]; j--; }
            sl[j + 1] = v;
        }
        g_nhubs = m;
        #pragma unroll
        for (int k = 0; k < 5; k++) {
            int v = (k < m) ? sl[k] : -1;
            g_hubs[k] = v;
            shub[k] = v;
        }
    }
    __syncthreads();
    for (int r = t; r < n; r += 1024) {
        int e0 = edges[r * 5 + 0], e1 = edges[r * 5 + 1], e2 = edges[r * 5 + 2];
        int e3 = edges[r * 5 + 3], e4 = edges[r * 5 + 4];
        unsigned m = 0;
        #pragma unroll
        for (int k = 0; k < 5; k++) {
            int hv = shub[k];
            bool hit = (hv >= 0) &&
                       (e0 == hv || e1 == hv || e2 == hv || e3 == hv || e4 == hv || r == hv);
            if (hit) m |= 1u << k;
        }
        mask[r] = (unsigned char)m;
    }
}

// ============================================================================
// Mega GEMM (FFMA2) + base hA + hub partials + zdot/score/keys epilogue
// (R15-verbatim; part stores coalesced in [ch][k][f])
// ============================================================================
__global__ void gemmF_kernel(const float* __restrict__ h, const float* __restrict__ W,
                             const float* __restrict__ b, const float* __restrict__ Wp,
                             const float* __restrict__ bp, const float* __restrict__ dinv,
                             const unsigned char* __restrict__ mask,
                             float* __restrict__ hA, float* __restrict__ part,
                             float* __restrict__ z, float* __restrict__ score,
                             unsigned long long* __restrict__ keys) {
    __shared__ __align__(16) float sbuf[HDIM * 34];
    __shared__ float spart[5 * HDIM];
    __shared__ float sdi[RPB];
    __shared__ float sWp[HDIM];
    const int t = threadIdx.x;
    const int c = t & 127;
    const int rb = (t >> 7) * 16;
    const int r0 = blockIdx.x * RPB;
    if (t < RPB) sdi[t] = dinv[r0 + t];
    if (t < HDIM) sWp[t] = Wp[t];
    #pragma unroll
    for (int l = 0; l < 16; l++) {
        int id = l * 256 + t;
        int rr = id >> 7, cc = id & 127;
        sbuf[cc * 34 + rr] = h[(size_t)(r0 + rr) * HDIM + cc];
    }
    __syncthreads();

    unsigned long long acc2[8];
    #pragma unroll
    for (int p = 0; p < 8; p++) acc2[p] = 0ull;
    #pragma unroll
    for (int k0 = 0; k0 < HDIM; k0 += 8) {
        float wv[8];
        #pragma unroll
        for (int q = 0; q < 8; q++) wv[q] = W[(k0 + q) * HDIM + c];
        #pragma unroll
        for (int q = 0; q < 8; q++) {
            unsigned long long w2 = pk2(wv[q], wv[q]);
            const float2* hp = (const float2*)&sbuf[(k0 + q) * 34 + rb];
            #pragma unroll
            for (int p = 0; p < 8; p++) {
                float2 h2 = hp[p];
                fma2(acc2[p], pk2(h2.x, h2.y), w2);
            }
        }
    }
    __syncthreads();

    unsigned long long um0 = *(const unsigned long long*)(mask + r0 + rb);
    unsigned long long um1 = *(const unsigned long long*)(mask + r0 + rb + 8);

    float bc = b[c];
    float hp5[5] = {0.f, 0.f, 0.f, 0.f, 0.f};
    #pragma unroll
    for (int p = 0; p < 8; p++) {
        float a0, a1;
        up2(acc2[p], a0, a1);
        int rr0 = rb + 2 * p, rr1 = rr0 + 1;
        float d0 = sdi[rr0], d1 = sdi[rr1];
        float v0 = fmaxf(fmaf(d0 * d0, a0, bc), 0.f);
        float v1 = fmaxf(fmaf(d1 * d1, a1, bc), 0.f);
        hA[(size_t)(r0 + rr0) * HDIM + c] = v0;
        hA[(size_t)(r0 + rr1) * HDIM + c] = v1;
        sbuf[rr0 * HDIM + c] = v0;
        sbuf[rr1 * HDIM + c] = v1;
        unsigned long long umm = (2 * p < 8) ? um0 : um1;
        unsigned mb0 = (unsigned)(umm >> (8 * ((2 * p) & 7))) & 0xffu;
        unsigned mb1 = (unsigned)(umm >> (8 * ((2 * p + 1) & 7))) & 0xffu;
        float w0 = d0 * a0, w1 = d1 * a1;
        #pragma unroll
        for (int k = 0; k < 5; k++) {
            if ((mb0 >> k) & 1u) hp5[k] += w0;
            if ((mb1 >> k) & 1u) hp5[k] += w1;
        }
    }
    if (rb == 16) {
        #pragma unroll
        for (int k = 0; k < 5; k++) spart[k * HDIM + c] = hp5[k];
    }
    __syncthreads();
    if (rb == 0) {
        #pragma unroll
        for (int k = 0; k < 5; k++)
            part[((size_t)blockIdx.x * 5 + k) * HDIM + c] = hp5[k] + spart[k * HDIM + c];
    }

    int w = t >> 5, lane = t & 31;
    float bp0 = bp[0];
    #pragma unroll
    for (int q = 0; q < 4; q++) {
        int rr = w * 4 + q;
        float s = 0.f;
        #pragma unroll
        for (int kk = 0; kk < 4; kk++)
            s = fmaf(sbuf[rr * HDIM + lane + 32 * kk], sWp[lane + 32 * kk], s);
        #pragma unroll
        for (int o = 16; o > 0; o >>= 1) s += __shfl_down_sync(0xffffffffu, s, o);
        if (lane == 0) {
            int r = r0 + rr;
            z[r] = s;
            float dc = sdi[rr];
            float sc = fmaf(dc * dc, s, bp0);
            score[r] = sc;
            keys[r] = ((unsigned long long)(~ordf(sc)) << 32) | (unsigned)r;
        }
    }
}

// ============================================================================
// Hub fixup (R13/R15: 5 blocks x 1024 threads, 8-slice ascending regroup)
// ============================================================================
__global__ void hubfixF_kernel(const float* __restrict__ part, int nchunks,
                               const float* __restrict__ dinv,
                               const float* __restrict__ b, const float* __restrict__ Wp,
                               float* __restrict__ hA, float* __restrict__ z) {
    int k = blockIdx.x;
    if (k >= g_nhubs) return;
    __shared__ float pp[8][HDIM];
    __shared__ float hv[HDIM];
    int t = threadIdx.x;
    int j = t >> 7, f = t & 127;
    int per = nchunks >> 3;
    int c0 = j * per;
    float S = 0.f;
    #pragma unroll 4
    for (int ch = c0; ch < c0 + per; ch++)
        S += part[((size_t)ch * 5 + k) * HDIM + f];
    pp[j][f] = S;
    __syncthreads();
    if (j == 0) {
        float T = S;
        #pragma unroll
        for (int q = 1; q < 8; q++) T += pp[q][f];
        int c = g_hubs[k];
        float v = fmaf(dinv[c], T, b[f]);
        v = fmaxf(v, 0.f);
        hA[(size_t)c * HDIM + f] = v;
        hv[f] = v;
    }
    __syncthreads();
    if (t < 32) {
        float s = 0.f;
        #pragma unroll
        for (int kk = 0; kk < 4; kk++)
            s = fmaf(hv[t + 32 * kk], Wp[t + 32 * kk], s);
        #pragma unroll
        for (int o = 16; o > 0; o >>= 1) s += __shfl_down_sync(0xffffffffu, s, o);
        if (t == 0) z[g_hubs[k]] = s;
    }
}

// R4-verbatim hub score + key pack
__global__ void hubfixSK_kernel(const float* __restrict__ z, const float* __restrict__ dinv,
                                const unsigned char* __restrict__ mask,
                                const float* __restrict__ bp,
                                float* __restrict__ score,
                                unsigned long long* __restrict__ keys, int n) {
    int k = blockIdx.x;
    if (k >= g_nhubs) return;
    int hub = g_hubs[k];
    __shared__ float red[256];
    int t = threadIdx.x;
    float p = 0.f;
    for (int r = t; r < n; r += 256) {
        if ((mask[r] >> k) & 1u) p += dinv[r] * z[r];
    }
    red[t] = p;
    __syncthreads();
    for (int o = 128; o > 0; o >>= 1) {
        if (t < o) red[t] += red[t + o];
        __syncthreads();
    }
    if (t == 0) {
        float sc = fmaf(dinv[hub], red[0], bp[0]);
        score[hub] = sc;
        keys[hub] = ((unsigned long long)(~ordf(sc)) << 32) | (unsigned)hub;
    }
}

// ============================================================================
// Multi-block bitonic sort, 2048-chunk + fused extract
// ============================================================================
__device__ __forceinline__ void do_extract2(const unsigned long long* sk, int g0, int t,
                                            const float* __restrict__ score,
                                            int* __restrict__ idx, float* __restrict__ sv,
                                            int* __restrict__ newid, int* __restrict__ indeg,
                                            int ksel) {
    #pragma unroll
    for (int h = 0; h < 2; h++) {
        int li = t + h * 1024;
        int i = g0 + li;
        int id = (int)(sk[li] & 0xffffffffull);
        newid[id] = (i < ksel) ? i : -1;
        if (i < ksel) {
            idx[i] = id;
            sv[i] = score[id];
            indeg[i] = 0;
        }
    }
}

__global__ void sort_local_kernel(unsigned long long* __restrict__ keys,
                                  const float* __restrict__ score,
                                  int* __restrict__ idx, float* __restrict__ sv,
                                  int* __restrict__ newid, int* __restrict__ indeg,
                                  int ksel, int do_ext) {
    __shared__ unsigned long long sk[CHUNK];
    int t = threadIdx.x;
    int g0 = blockIdx.x * CHUNK;
    sk[t] = keys[g0 + t];
    sk[t + 1024] = keys[g0 + t + 1024];
    __syncthreads();
    for (int k = 2; k <= CHUNK; k <<= 1) {
        for (int j = k >> 1; j > 0; j >>= 1) {
            int i = ((t / j) * 2 * j) + (t % j);
            int ixj = i + j;
            bool up = (((g0 + i) & k) == 0);
            unsigned long long a = sk[i], bb = sk[ixj];
            if ((a > bb) == up) { sk[i] = bb; sk[ixj] = a; }
            __syncthreads();
        }
    }
    keys[g0 + t] = sk[t];
    keys[g0 + t + 1024] = sk[t + 1024];
    if (do_ext) do_extract2(sk, g0, t, score, idx, sv, newid, indeg, ksel);
}

__global__ void sort_cross_kernel(unsigned long long* __restrict__ keys,
                                  int n, int k, int j) {
    int t = blockIdx.x * 256 + threadIdx.x;
    if (t >= n / 2) return;
    int i = ((t / j) * 2 * j) + (t % j);
    int ixj = i + j;
    bool up = ((i & k) == 0);
    unsigned long long a = keys[i], bb = keys[ixj];
    if ((a > bb) == up) { keys[i] = bb; keys[ixj] = a; }
}

__global__ void sort_finish_kernel(unsigned long long* __restrict__ keys, int k,
                                   const float* __restrict__ score,
                                   int* __restrict__ idx, float* __restrict__ sv,
                                   int* __restrict__ newid, int* __restrict__ indeg,
                                   int ksel, int do_ext) {
    __shared__ unsigned long long sk[CHUNK];
    int t = threadIdx.x;
    int g0 = blockIdx.x * CHUNK;
    sk[t] = keys[g0 + t];
    sk[t + 1024] = keys[g0 + t + 1024];
    __syncthreads();
    for (int j = 1024; j > 0; j >>= 1) {
        int i = ((t / j) * 2 * j) + (t % j);
        int ixj = i + j;
        bool up = (((g0 + i) & k) == 0);
        unsigned long long a = sk[i], bb = sk[ixj];
        if ((a > bb) == up) { sk[i] = bb; sk[ixj] = a; }
        __syncthreads();
    }
    keys[g0 + t] = sk[t];
    keys[g0 + t + 1024] = sk[t + 1024];
    if (do_ext) do_extract2(sk, g0, t, score, idx, sv, newid, indeg, ksel);
}

// ============================================================================
// Pool (32 new nodes/block)
// ============================================================================
__global__ void pool_kernel(const float* __restrict__ h, const float* __restrict__ xs,
                            const int* __restrict__ perm, const int* __restrict__ edges,
                            const int* __restrict__ idx, const float* __restrict__ sv,
                            const int* __restrict__ newid,
                            float* __restrict__ h2, float* __restrict__ xs2,
                            int* __restrict__ perm2, int* __restrict__ edges2,
                            int* __restrict__ indeg, int stage) {
    __shared__ int sidx[32];
    __shared__ float sg[32];
    int c = threadIdx.x;
    int a0 = blockIdx.x * 32;
    if (c < 32) {
        sidx[c] = idx[a0 + c];
        sg[c] = tanhf(sv[a0 + c]);
    }
    __syncthreads();
    float lmax = -3.4e38f, lsum = 0.f;
    for (int rr = 0; rr < 32; rr++) {
        int a = a0 + rr;
        int o = sidx[rr];
        float v = h[(size_t)o * HDIM + c] * sg[rr];
        h2[(size_t)a * HDIM + c] = v;
        xs2[(size_t)a * HDIM + c] = xs[(size_t)o * HDIM + c];
        lmax = fmaxf(lmax, v);
        lsum += v;
        if (c < 5) {
            int e = edges[o * 5 + c];
            int ne = (e >= 0) ? newid[e] : -1;
            edges2[a * 5 + c] = ne;
            if (ne >= 0) atomicAdd(&indeg[ne], 1);
        }
        if (c == 5) perm2[a] = (perm != nullptr) ? perm[o] : o;
    }
    atomicMax(&g_rmax[stage][c], ordf(lmax));
    atomicAdd(&g_rsum[stage][c], lsum);
}

// ============================================================================
// Tail: a3 densify (blocks 0..1023) + xs/perm copy (1024..1539) + MLP (1540)
// ============================================================================
__global__ void tail_kernel(const int* __restrict__ edges,
                            const float* __restrict__ xs, const int* __restrict__ perm,
                            const float* __restrict__ L1w, const float* __restrict__ L1b,
                            const float* __restrict__ L2w, const float* __restrict__ L2b,
                            const float* __restrict__ L3w, const float* __restrict__ L3b,
                            float* __restrict__ out) {
    int bidx = blockIdx.x;
    int t = threadIdx.x;
    if (bidx < 1024) {
        float* row = out + 40 + 1024 * HDIM + 1024 + (size_t)bidx * 1024;
        for (int i = t; i < 1024; i += 256) row[i] = 0.f;
        __syncthreads();
        if (t == 0) {
            row[bidx] = 1.f;
            #pragma unroll
            for (int e = 0; e < 5; e++) {
                int tgt = edges[bidx * 5 + e];
                if (tgt >= 0) row[tgt] = 1.f;
            }
        }
        return;
    }
    if (bidx < 1540) {
        int i = (bidx - 1024) * 256 + t;
        if (i < 1024 * HDIM) out[40 + i] = xs[i];
        else if (i < 1024 * HDIM + 1024)
            out[40 + 1024 * HDIM + (i - 1024 * HDIM)] = (float)perm[i - 1024 * HDIM];
        return;
    }
    __shared__ float zin[256], z1[128], z2[64], z3[40];
    if (t < 128) {
        zin[t] = deco(g_rmax[0][t]) + deco(g_rmax[1][t]) + deco(g_rmax[2][t]);
        zin[128 + t] = g_rsum[0][t] / 4096.f + g_rsum[1][t] / 2048.f + g_rsum[2][t] / 1024.f;
    }
    __syncthreads();
    if (t < 128) {
        float a = 0.f;
        for (int i = 0; i < 256; i++) a = fmaf(zin[i], L1w[i * 128 + t], a);
        z1[t] = fmaxf(a + L1b[t], 0.f);
    }
    __syncthreads();
    if (t < 64) {
        float a = 0.f;
        for (int i = 0; i < 128; i++) a = fmaf(z1[i], L2w[i * 64 + t], a);
        z2[t] = fmaxf(a + L2b[t], 0.f);
    }
    __syncthreads();
    if (t < 40) {
        float a = 0.f;
        for (int i = 0; i < 64; i++) a = fmaf(z2[i], L3w[i * 40 + t], a);
        z3[t] = a + L3b[t];
    }
    __syncthreads();
    if (t == 0) {
        float m = z3[0];
        for (int i = 1; i < 40; i++) m = fmaxf(m, z3[i]);
        float s = 0.f;
        for (int i = 0; i < 40; i++) s += expf(z3[i] - m);
        float l = m + logf(s);
        for (int i = 0; i < 40; i++) out[i] = z3[i] - l;
    }
}

// ============================================================================
// Host launcher
// ============================================================================
extern "C" void kernel_launch(void* const* d_in, const int* in_sizes, int n_in,
                              void* d_out, int out_size) {
    (void)in_sizes; (void)n_in; (void)out_size;
    const float* x0  = (const float*)d_in[0];
    const float* W[3]  = {(const float*)d_in[2], (const float*)d_in[4], (const float*)d_in[6]};
    const float* bb[3] = {(const float*)d_in[3], (const float*)d_in[5], (const float*)d_in[7]};
    const float* Wp[3] = {(const float*)d_in[8], (const float*)d_in[10], (const float*)d_in[12]};
    const float* bp[3] = {(const float*)d_in[9], (const float*)d_in[11], (const float*)d_in[13]};
    const float* L1w = (const float*)d_in[14];
    const float* L1b = (const float*)d_in[15];
    const float* L2w = (const float*)d_in[16];
    const float* L2b = (const float*)d_in[17];
    const float* L3w = (const float*)d_in[18];
    const float* L3b = (const float*)d_in[19];
    float* out = (float*)d_out;

    float *p_hA, *p_hB, *p_dinv, *p_z, *p_score, *p_sv, *p_xsb, *p_part;
    int *p_edgesb, *p_indeg, *p_idx, *p_newid, *p_permb;
    unsigned char* p_mask;
    unsigned long long* p_keys;
    cudaGetSymbolAddress((void**)&p_edgesb, g_edges);
    cudaGetSymbolAddress((void**)&p_hA, g_hA);
    cudaGetSymbolAddress((void**)&p_hB, g_hB);
    cudaGetSymbolAddress((void**)&p_xsb, g_xs);
    cudaGetSymbolAddress((void**)&p_permb, g_perm);
    cudaGetSymbolAddress((void**)&p_indeg, g_indeg);
    cudaGetSymbolAddress((void**)&p_dinv, g_dinv);
    cudaGetSymbolAddress((void**)&p_z, g_z);
    cudaGetSymbolAddress((void**)&p_score, g_score);
    cudaGetSymbolAddress((void**)&p_keys, g_keys);
    cudaGetSymbolAddress((void**)&p_idx, g_idx);
    cudaGetSymbolAddress((void**)&p_sv, g_sv);
    cudaGetSymbolAddress((void**)&p_newid, g_newid);
    cudaGetSymbolAddress((void**)&p_part, g_part);
    cudaGetSymbolAddress((void**)&p_mask, g_mask);

    int* p_edges[2] = {p_edgesb, p_edgesb + NMAX * 5};
    float* p_xs[2] = {p_xsb, p_xsb + (size_t)NMAX * HDIM};
    int* p_perm[2] = {p_permb, p_permb + NMAX};

    // init: edges0, closed-form indeg + stage-0 dinv/mask/hubs, readout zero
    init_kernel<<<NMAX / 256, 256>>>(p_edges[0], p_indeg, p_dinv, p_mask);

    for (int s = 0; s < 3; s++) {
        int n = NMAX >> s;
        int k = n >> 1;
        int nchunks = n / RPB;
        int* ecur = p_edges[s & 1];
        int* enext = p_edges[(s + 1) & 1];
        const float* hin = (s == 0) ? x0 : p_hB;
        const float* xin = (s == 0) ? x0 : p_xs[(s - 1) & 1];
        const int* pin = (s == 0) ? nullptr : p_perm[(s - 1) & 1];

        if (s > 0)
            dinvhubsmask_kernel<<<1, 1024>>>(p_indeg, ecur, p_dinv, p_mask, n);

        gemmF_kernel<<<nchunks, 256>>>(hin, W[s], bb[s], Wp[s], bp[s], p_dinv,
                                       p_mask, p_hA, p_part, p_z, p_score, p_keys);
        hubfixF_kernel<<<5, 1024>>>(p_part, nchunks, p_dinv, bb[s], Wp[s], p_hA, p_z);
        hubfixSK_kernel<<<5, 256>>>(p_z, p_dinv, p_mask, bp[s], p_score, p_keys, n);

        // multiblock bitonic sort, 2048-chunk (+ fused extract on final pass)
        int nblk = n / CHUNK;
        sort_local_kernel<<<nblk, 1024>>>(p_keys, p_score, p_idx, p_sv,
                                          p_newid, p_indeg, k, (n == CHUNK) ? 1 : 0);
        for (int kk = 2 * CHUNK; kk <= n; kk <<= 1) {
            for (int j = kk >> 1; j >= CHUNK; j >>= 1)
                sort_cross_kernel<<<(n / 2 + 255) / 256, 256>>>(p_keys, n, kk, j);
            sort_finish_kernel<<<nblk, 1024>>>(p_keys, kk, p_score, p_idx, p_sv,
                                               p_newid, p_indeg, k,
                                               (kk == n) ? 1 : 0);
        }

        pool_kernel<<<k / 32, 128>>>(p_hA, xin, pin, ecur, p_idx, p_sv, p_newid,
                                     p_hB, p_xs[s & 1], p_perm[s & 1], enext,
                                     p_indeg, s);
    }

    tail_kernel<<<1541, 256>>>(p_edges[1], p_xs[0], p_perm[0],
                               L1w, L1b, L2w, L2b, L3w, L3b, out);
}